// round 2
// baseline (speedup 1.0000x reference)
#include <cuda_runtime.h>

#define D_MODEL 256
#define NHEAD   8
#define DH      32
#define SEQ     2048
#define NB      4
#define EPSV    1e-9f
#define SCALE   0.17677669529663687f   /* 1/sqrt(32) */

typedef unsigned long long ull;

/* ---------------- scratch (no allocations allowed) ---------------- */
__device__ float g_q [NB*SEQ*D_MODEL];
__device__ float g_k [SEQ*D_MODEL];
__device__ float g_v [NB*SEQ*D_MODEL];
__device__ float g_rs[NB*SEQ];
__device__ float g_o [NB*SEQ*D_MODEL];

/* ---------------- f32x2 packed-math helpers ---------------- */
__device__ __forceinline__ ull pk2(float x, float y) {
    ull r; asm("mov.b64 %0, {%1,%2};" : "=l"(r) : "f"(x), "f"(y)); return r;
}
__device__ __forceinline__ ull fma2(ull a, ull b, ull c) {
    ull d; asm("fma.rn.f32x2 %0, %1, %2, %3;" : "=l"(d) : "l"(a), "l"(b), "l"(c)); return d;
}
__device__ __forceinline__ float2 upk(ull v) {
    float x, y; asm("mov.b64 {%0,%1}, %2;" : "=f"(x), "=f"(y) : "l"(v));
    float2 r; r.x = x; r.y = y; return r;
}

/* =================================================================
 * GEMM body: C[M,256] = A[M,256] @ W[256,256]^T + bias
 * BM=64 BN=64 BK=32, 256 threads, thread tile 4m x 4n (f32x2 over n)
 * ================================================================= */
__device__ __forceinline__ void gemm_body(
    const float* __restrict__ A, const float* __restrict__ W,
    const float* __restrict__ bias, float* __restrict__ C,
    int row0, int col0, float* sA, float* sB)
{
    const int t  = threadIdx.x;
    const int tx = t & 15, ty = t >> 4;
    const int m0 = ty * 4, n0 = tx * 4;

    ull acc[4][2];
#pragma unroll
    for (int i = 0; i < 4; i++) { acc[i][0] = 0ull; acc[i][1] = 0ull; }

    const int fm = t >> 2, fk = (t & 3) * 8;
    const int fn = t & 63, fkc = (t >> 6) * 8;

    for (int kt = 0; kt < 8; kt++) {
        const float4* pa = (const float4*)(A + (size_t)(row0 + fm) * 256 + kt * 32 + fk);
        float4 a0 = pa[0], a1 = pa[1];
        *(float4*)&sA[fm * 36 + fk]     = a0;
        *(float4*)&sA[fm * 36 + fk + 4] = a1;
        const float4* pw = (const float4*)(W + (size_t)(col0 + fn) * 256 + kt * 32 + fkc);
        float4 w0 = pw[0], w1 = pw[1];
        sB[(fkc + 0) * 64 + fn] = w0.x; sB[(fkc + 1) * 64 + fn] = w0.y;
        sB[(fkc + 2) * 64 + fn] = w0.z; sB[(fkc + 3) * 64 + fn] = w0.w;
        sB[(fkc + 4) * 64 + fn] = w1.x; sB[(fkc + 5) * 64 + fn] = w1.y;
        sB[(fkc + 6) * 64 + fn] = w1.z; sB[(fkc + 7) * 64 + fn] = w1.w;
        __syncthreads();

#pragma unroll
        for (int k4 = 0; k4 < 8; k4++) {
            float4 av[4];
#pragma unroll
            for (int i = 0; i < 4; i++)
                av[i] = *(const float4*)&sA[(m0 + i) * 36 + k4 * 4];
#pragma unroll
            for (int c = 0; c < 4; c++) {
                ulonglong2 bb = *(const ulonglong2*)&sB[(k4 * 4 + c) * 64 + n0];
#pragma unroll
                for (int i = 0; i < 4; i++) {
                    float a = (c == 0) ? av[i].x : (c == 1) ? av[i].y : (c == 2) ? av[i].z : av[i].w;
                    ull ad = pk2(a, a);
                    acc[i][0] = fma2(ad, bb.x, acc[i][0]);
                    acc[i][1] = fma2(ad, bb.y, acc[i][1]);
                }
            }
        }
        __syncthreads();
    }

    float4 bi = *(const float4*)&bias[col0 + n0];
#pragma unroll
    for (int i = 0; i < 4; i++) {
        float2 r0 = upk(acc[i][0]), r1 = upk(acc[i][1]);
        float4 o; o.x = r0.x + bi.x; o.y = r0.y + bi.y; o.z = r1.x + bi.z; o.w = r1.y + bi.w;
        *(float4*)&C[(size_t)(row0 + m0 + i) * 256 + col0 + n0] = o;
    }
}

/* single GEMM (used for fc) */
__global__ void __launch_bounds__(256) gemm256(
    const float* __restrict__ A, const float* __restrict__ W,
    const float* __restrict__ bias, float* __restrict__ C)
{
    __shared__ float sA[64 * 36];
    __shared__ float sB[32 * 64];
    gemm_body(A, W, bias, C, blockIdx.x * 64, blockIdx.y * 64, sA, sB);
}

/* merged q/v/k projection GEMMs (z selects which) */
__global__ void __launch_bounds__(256) gemm_proj(
    const float* __restrict__ Aq, const float* __restrict__ Wq, const float* __restrict__ bq, float* __restrict__ Cq,
    const float* __restrict__ Av, const float* __restrict__ Wv, const float* __restrict__ bv, float* __restrict__ Cv,
    const float* __restrict__ Ak, const float* __restrict__ Wk, const float* __restrict__ bk, float* __restrict__ Ck)
{
    __shared__ float sA[64 * 36];
    __shared__ float sB[32 * 64];
    const int z = blockIdx.z;
    const float* A; const float* W; const float* bia; float* C;
    if (z == 0)      { A = Aq; W = Wq; bia = bq; C = Cq; }
    else if (z == 1) { A = Av; W = Wv; bia = bv; C = Cv; }
    else             { A = Ak; W = Wk; bia = bk; C = Ck;
                       if (blockIdx.x >= 32) return; }   /* keys: M=2048 only */
    gemm_body(A, W, bia, C, blockIdx.x * 64, blockIdx.y * 64, sA, sB);
}

/* =================================================================
 * Row-wise: g_rs[row] = 1 / sum_s 1/(dist[row][s]+eps)   (fast rcp)
 * ================================================================= */
__global__ void __launch_bounds__(256) rsumk(
    const float* __restrict__ dist, float* __restrict__ out)
{
    const int row = blockIdx.x;
    const float4* p = (const float4*)(dist + (size_t)row * 2048);
    const int t = threadIdx.x;

    float s = 0.f;
#pragma unroll
    for (int it = 0; it < 2; it++) {
        float4 x = p[t + it * 256];
        s += __fdividef(1.0f, x.x + EPSV) + __fdividef(1.0f, x.y + EPSV)
           + __fdividef(1.0f, x.z + EPSV) + __fdividef(1.0f, x.w + EPSV);
    }
#pragma unroll
    for (int off = 16; off > 0; off >>= 1)
        s += __shfl_xor_sync(0xffffffffu, s, off);

    __shared__ float red[8];
    if ((t & 31) == 0) red[t >> 5] = s;
    __syncthreads();
    if (t == 0) {
        float tot = 0.f;
#pragma unroll
        for (int w = 0; w < 8; w++) tot += red[w];
        out[row] = 1.0f / tot;
    }
}

/* =================================================================
 * Fused attention. Block = (batch b, 32 q-rows, 8 heads). warp = head.
 * Thread tile 4q x 8s (scores) / 4q x 8d (output).
 * P matrix is staged through the (dead-after-QK) per-head sKt slice:
 *   no p[] register array, no PV shuffles, no spills.
 * ================================================================= */
#define ATTN_SMEM_FLOATS (8192 + 9216 + 8192 + 1280 + 32)

__global__ void __launch_bounds__(256, 2) attnk(
    const float* __restrict__ Q, const float* __restrict__ K,
    const float* __restrict__ V, const float* __restrict__ DIST,
    const float* __restrict__ RS, float* __restrict__ O)
{
    extern __shared__ float sm[];
    float* sQt = sm;            /* [256 dims][32 q]                       */
    float* sKt = sm + 8192;     /* [256 dims][32 s] stride 36 (+P reuse)  */
    float* sV  = sm + 17408;    /* [32 s][256 dims]                       */
    float* sW  = sm + 25600;    /* [32 q][32 s] stride 40                 */
    float* sRs = sm + 26880;    /* [32 q]                                 */

    const int b  = blockIdx.y;
    const int qb = blockIdx.x * 32;
    const int t  = threadIdx.x;
    const int lane = t & 31, h = t >> 5;
    const int uq = lane & 7, us = lane >> 3;
    const int q0 = uq * 4, s0 = us * 8, d0 = us * 8;
    const int kb = h * 32;
    float* sP = sKt + kb * 36;  /* per-head P: [32 q][stride 33], fits 32*36 slice */

    /* ---- fill Q transposed (scale folded) + rs ---- */
    {
        const int qq = t & 31, dc = (t >> 5) * 32;
        const float* src = Q + (size_t)(b * SEQ + qb + qq) * 256 + dc;
#pragma unroll
        for (int c = 0; c < 8; c++) {
            float4 x = *(const float4*)(src + c * 4);
            int d = dc + c * 4;
            sQt[(d + 0) * 32 + qq] = x.x * SCALE;
            sQt[(d + 1) * 32 + qq] = x.y * SCALE;
            sQt[(d + 2) * 32 + qq] = x.z * SCALE;
            sQt[(d + 3) * 32 + qq] = x.w * SCALE;
        }
        if (t < 32) sRs[t] = RS[b * SEQ + qb + t];
    }
    __syncthreads();

    ull oacc[4][4];
#pragma unroll
    for (int i = 0; i < 4; i++)
#pragma unroll
        for (int j = 0; j < 4; j++) oacc[i][j] = 0ull;
    float rden[4] = {0.f, 0.f, 0.f, 0.f};

    for (int st = 0; st < 64; st++) {
        const int sb = st * 32;

        /* ---- fill K transposed ---- */
        {
            const int ss = t & 31, dc = (t >> 5) * 32;
            const float* src = K + (size_t)(sb + ss) * 256 + dc;
#pragma unroll
            for (int c = 0; c < 8; c++) {
                float4 x = *(const float4*)(src + c * 4);
                int d = dc + c * 4;
                sKt[(d + 0) * 36 + ss] = x.x;
                sKt[(d + 1) * 36 + ss] = x.y;
                sKt[(d + 2) * 36 + ss] = x.z;
                sKt[(d + 3) * 36 + ss] = x.w;
            }
        }
        /* ---- fill V row-major ---- */
        {
            const int ss = t >> 3, dc = (t & 7) * 32;
            const float4* src = (const float4*)(V + (size_t)(b * SEQ + sb + ss) * 256 + dc);
            float4* dst = (float4*)(sV + ss * 256 + dc);
#pragma unroll
            for (int c = 0; c < 8; c++) dst[c] = src[c];
        }
        /* ---- fill distance weights w = rs / (d + eps)  (fast rcp) ---- */
        {
            const int qq = t >> 3, sc = (t & 7) * 4;
            float4 dd = *(const float4*)(DIST + (size_t)(b * SEQ + qb + qq) * 2048 + sb + sc);
            float rs = sRs[qq];
            float4 w;
            w.x = __fdividef(rs, dd.x + EPSV);
            w.y = __fdividef(rs, dd.y + EPSV);
            w.z = __fdividef(rs, dd.z + EPSV);
            w.w = __fdividef(rs, dd.w + EPSV);
            *(float4*)&sW[qq * 40 + sc] = w;
        }
        __syncthreads();

        /* ---- QK^T scores: 32x32 per head, f32x2 over s-pairs ---- */
        ull racc[4][4];
#pragma unroll
        for (int i = 0; i < 4; i++)
#pragma unroll
            for (int j = 0; j < 4; j++) racc[i][j] = 0ull;

#pragma unroll 4
        for (int c = 0; c < 32; c++) {
            float4 qv = *(const float4*)&sQt[(kb + c) * 32 + q0];
            ulonglong2 b0 = *(const ulonglong2*)&sKt[(kb + c) * 36 + s0];
            ulonglong2 b1 = *(const ulonglong2*)&sKt[(kb + c) * 36 + s0 + 4];
            ull a;
            a = pk2(qv.x, qv.x);
            racc[0][0] = fma2(a, b0.x, racc[0][0]); racc[0][1] = fma2(a, b0.y, racc[0][1]);
            racc[0][2] = fma2(a, b1.x, racc[0][2]); racc[0][3] = fma2(a, b1.y, racc[0][3]);
            a = pk2(qv.y, qv.y);
            racc[1][0] = fma2(a, b0.x, racc[1][0]); racc[1][1] = fma2(a, b0.y, racc[1][1]);
            racc[1][2] = fma2(a, b1.x, racc[1][2]); racc[1][3] = fma2(a, b1.y, racc[1][3]);
            a = pk2(qv.z, qv.z);
            racc[2][0] = fma2(a, b0.x, racc[2][0]); racc[2][1] = fma2(a, b0.y, racc[2][1]);
            racc[2][2] = fma2(a, b1.x, racc[2][2]); racc[2][3] = fma2(a, b1.y, racc[2][3]);
            a = pk2(qv.w, qv.w);
            racc[3][0] = fma2(a, b0.x, racc[3][0]); racc[3][1] = fma2(a, b0.y, racc[3][1]);
            racc[3][2] = fma2(a, b1.x, racc[3][2]); racc[3][3] = fma2(a, b1.y, racc[3][3]);
        }

        /* warp-level fence: all lanes done reading this head's sKt slice
           before we overwrite it with P */
        __syncwarp();

        /* ---- p = exp(score * dw); stage P into the dead sKt slice ---- */
#pragma unroll
        for (int i = 0; i < 4; i++) {
            const float* wr = &sW[(q0 + i) * 40 + s0];
            float4 wa = *(const float4*)wr;
            float4 wb = *(const float4*)(wr + 4);
            float2 x0 = upk(racc[i][0]), x1 = upk(racc[i][1]);
            float2 x2 = upk(racc[i][2]), x3 = upk(racc[i][3]);
            float p0 = __expf(x0.x * wa.x), p1 = __expf(x0.y * wa.y);
            float p2 = __expf(x1.x * wa.z), p3 = __expf(x1.y * wa.w);
            float p4 = __expf(x2.x * wb.x), p5 = __expf(x2.y * wb.y);
            float p6 = __expf(x3.x * wb.z), p7 = __expf(x3.y * wb.w);
            float dl = ((p0 + p1) + (p2 + p3)) + ((p4 + p5) + (p6 + p7));
            dl += __shfl_xor_sync(0xffffffffu, dl, 8);
            dl += __shfl_xor_sync(0xffffffffu, dl, 16);
            rden[i] += dl;
            float* pp = &sP[(q0 + i) * 33 + s0];
            pp[0] = p0; pp[1] = p1; pp[2] = p2; pp[3] = p3;
            pp[4] = p4; pp[5] = p5; pp[6] = p6; pp[7] = p7;
        }
        __syncwarp();

        /* ---- P @ V : p via conflict-free scalar LDS broadcast ---- */
#pragma unroll 4
        for (int s = 0; s < 32; s++) {
            const float* vr = &sV[s * 256 + kb + d0];
            ulonglong2 v0 = *(const ulonglong2*)vr;
            ulonglong2 v1 = *(const ulonglong2*)(vr + 4);
#pragma unroll
            for (int i = 0; i < 4; i++) {
                float pi = sP[(q0 + i) * 33 + s];
                ull a = pk2(pi, pi);
                oacc[i][0] = fma2(a, v0.x, oacc[i][0]);
                oacc[i][1] = fma2(a, v0.y, oacc[i][1]);
                oacc[i][2] = fma2(a, v1.x, oacc[i][2]);
                oacc[i][3] = fma2(a, v1.y, oacc[i][3]);
            }
        }
        __syncthreads();
    }

    /* ---- normalize + write ---- */
#pragma unroll
    for (int i = 0; i < 4; i++) {
        float inv = 1.0f / rden[i];
        float2 o0 = upk(oacc[i][0]), o1 = upk(oacc[i][1]);
        float2 o2 = upk(oacc[i][2]), o3 = upk(oacc[i][3]);
        float4 w0, w1;
        w0.x = o0.x * inv; w0.y = o0.y * inv; w0.z = o1.x * inv; w0.w = o1.y * inv;
        w1.x = o2.x * inv; w1.y = o2.y * inv; w1.z = o3.x * inv; w1.w = o3.y * inv;
        float* dst = O + (size_t)(b * SEQ + qb + q0 + i) * 256 + kb + d0;
        *(float4*)dst       = w0;
        *(float4*)(dst + 4) = w1;
    }
}

/* ================================================================= */
extern "C" void kernel_launch(void* const* d_in, const int* in_sizes, int n_in,
                              void* d_out, int out_size)
{
    const float* query  = (const float*)d_in[0];
    const float* values = (const float*)d_in[1];
    const float* dist   = (const float*)d_in[2];
    const float* Wq     = (const float*)d_in[3];
    const float* Wqb    = (const float*)d_in[4];
    const float* Wk     = (const float*)d_in[5];
    const float* Wkb    = (const float*)d_in[6];
    const float* Wv     = (const float*)d_in[7];
    const float* Wvb    = (const float*)d_in[8];
    const float* fcw    = (const float*)d_in[9];
    const float* fcb    = (const float*)d_in[10];
    const float* keys   = (const float*)d_in[11];
    float* out = (float*)d_out;

    void *pq, *pk, *pv, *prs, *po;
    cudaGetSymbolAddress(&pq,  g_q);
    cudaGetSymbolAddress(&pk,  g_k);
    cudaGetSymbolAddress(&pv,  g_v);
    cudaGetSymbolAddress(&prs, g_rs);
    cudaGetSymbolAddress(&po,  g_o);

    const int smem_bytes = ATTN_SMEM_FLOATS * 4;  /* 107648 */
    cudaFuncSetAttribute(attnk, cudaFuncAttributeMaxDynamicSharedMemorySize, smem_bytes);

    /* all three projections in one launch */
    gemm_proj<<<dim3(128, 4, 3), 256>>>(query,  Wq, Wqb, (float*)pq,
                                        values, Wv, Wvb, (float*)pv,
                                        keys,   Wk, Wkb, (float*)pk);
    /* distance-weight denominators */
    rsumk<<<NB * SEQ, 256>>>(dist, (float*)prs);
    /* fused attention */
    attnk<<<dim3(64, 4), 256, smem_bytes>>>((const float*)pq, (const float*)pk,
                                            (const float*)pv, dist,
                                            (const float*)prs, (float*)po);
    /* output projection */
    gemm256<<<dim3(128, 4), 256>>>((const float*)po, fcw, fcb, out);
}

// round 3
// speedup vs baseline: 1.0025x; 1.0025x over previous
#include <cuda_runtime.h>

#define D_MODEL 256
#define NHEAD   8
#define DH      32
#define SEQ     2048
#define NB      4
#define EPSV    1e-9f
#define SCALE   0.17677669529663687f   /* 1/sqrt(32) */

typedef unsigned long long ull;

/* ---------------- scratch (no allocations allowed) ---------------- */
__device__ float g_q [NB*SEQ*D_MODEL];
__device__ float g_k [SEQ*D_MODEL];
__device__ float g_v [NB*SEQ*D_MODEL];
__device__ float g_rs[NB*SEQ];
__device__ float g_o [NB*SEQ*D_MODEL];

/* ---------------- f32x2 packed-math helpers ---------------- */
__device__ __forceinline__ ull pk2(float x, float y) {
    ull r; asm("mov.b64 %0, {%1,%2};" : "=l"(r) : "f"(x), "f"(y)); return r;
}
__device__ __forceinline__ ull fma2(ull a, ull b, ull c) {
    ull d; asm("fma.rn.f32x2 %0, %1, %2, %3;" : "=l"(d) : "l"(a), "l"(b), "l"(c)); return d;
}
__device__ __forceinline__ float2 upk(ull v) {
    float x, y; asm("mov.b64 {%0,%1}, %2;" : "=f"(x), "=f"(y) : "l"(v));
    float2 r; r.x = x; r.y = y; return r;
}

/* =================================================================
 * GEMM body: C[M,256] = A[M,256] @ W[256,256]^T + bias
 * BM=64 BN=64 BK=32, 256 threads, thread tile 4m x 4n (f32x2 over n)
 * ================================================================= */
__device__ __forceinline__ void gemm_body(
    const float* __restrict__ A, const float* __restrict__ W,
    const float* __restrict__ bias, float* __restrict__ C,
    int row0, int col0, float* sA, float* sB)
{
    const int t  = threadIdx.x;
    const int tx = t & 15, ty = t >> 4;
    const int m0 = ty * 4, n0 = tx * 4;

    ull acc[4][2];
#pragma unroll
    for (int i = 0; i < 4; i++) { acc[i][0] = 0ull; acc[i][1] = 0ull; }

    const int fm = t >> 2, fk = (t & 3) * 8;
    const int fn = t & 63, fkc = (t >> 6) * 8;

    for (int kt = 0; kt < 8; kt++) {
        const float4* pa = (const float4*)(A + (size_t)(row0 + fm) * 256 + kt * 32 + fk);
        float4 a0 = pa[0], a1 = pa[1];
        *(float4*)&sA[fm * 36 + fk]     = a0;
        *(float4*)&sA[fm * 36 + fk + 4] = a1;
        const float4* pw = (const float4*)(W + (size_t)(col0 + fn) * 256 + kt * 32 + fkc);
        float4 w0 = pw[0], w1 = pw[1];
        sB[(fkc + 0) * 64 + fn] = w0.x; sB[(fkc + 1) * 64 + fn] = w0.y;
        sB[(fkc + 2) * 64 + fn] = w0.z; sB[(fkc + 3) * 64 + fn] = w0.w;
        sB[(fkc + 4) * 64 + fn] = w1.x; sB[(fkc + 5) * 64 + fn] = w1.y;
        sB[(fkc + 6) * 64 + fn] = w1.z; sB[(fkc + 7) * 64 + fn] = w1.w;
        __syncthreads();

#pragma unroll
        for (int k4 = 0; k4 < 8; k4++) {
            float4 av[4];
#pragma unroll
            for (int i = 0; i < 4; i++)
                av[i] = *(const float4*)&sA[(m0 + i) * 36 + k4 * 4];
#pragma unroll
            for (int c = 0; c < 4; c++) {
                ulonglong2 bb = *(const ulonglong2*)&sB[(k4 * 4 + c) * 64 + n0];
#pragma unroll
                for (int i = 0; i < 4; i++) {
                    float a = (c == 0) ? av[i].x : (c == 1) ? av[i].y : (c == 2) ? av[i].z : av[i].w;
                    ull ad = pk2(a, a);
                    acc[i][0] = fma2(ad, bb.x, acc[i][0]);
                    acc[i][1] = fma2(ad, bb.y, acc[i][1]);
                }
            }
        }
        __syncthreads();
    }

    float4 bi = *(const float4*)&bias[col0 + n0];
#pragma unroll
    for (int i = 0; i < 4; i++) {
        float2 r0 = upk(acc[i][0]), r1 = upk(acc[i][1]);
        float4 o; o.x = r0.x + bi.x; o.y = r0.y + bi.y; o.z = r1.x + bi.z; o.w = r1.y + bi.w;
        *(float4*)&C[(size_t)(row0 + m0 + i) * 256 + col0 + n0] = o;
    }
}

/* single GEMM (used for fc) */
__global__ void __launch_bounds__(256) gemm256(
    const float* __restrict__ A, const float* __restrict__ W,
    const float* __restrict__ bias, float* __restrict__ C)
{
    __shared__ float sA[64 * 36];
    __shared__ float sB[32 * 64];
    gemm_body(A, W, bias, C, blockIdx.x * 64, blockIdx.y * 64, sA, sB);
}

/* merged q/v/k projection GEMMs (z selects which) */
__global__ void __launch_bounds__(256) gemm_proj(
    const float* __restrict__ Aq, const float* __restrict__ Wq, const float* __restrict__ bq, float* __restrict__ Cq,
    const float* __restrict__ Av, const float* __restrict__ Wv, const float* __restrict__ bv, float* __restrict__ Cv,
    const float* __restrict__ Ak, const float* __restrict__ Wk, const float* __restrict__ bk, float* __restrict__ Ck)
{
    __shared__ float sA[64 * 36];
    __shared__ float sB[32 * 64];
    const int z = blockIdx.z;
    const float* A; const float* W; const float* bia; float* C;
    if (z == 0)      { A = Aq; W = Wq; bia = bq; C = Cq; }
    else if (z == 1) { A = Av; W = Wv; bia = bv; C = Cv; }
    else             { A = Ak; W = Wk; bia = bk; C = Ck;
                       if (blockIdx.x >= 32) return; }   /* keys: M=2048 only */
    gemm_body(A, W, bia, C, blockIdx.x * 64, blockIdx.y * 64, sA, sB);
}

/* =================================================================
 * Row-wise: g_rs[row] = 1 / sum_s 1/(dist[row][s]+eps)   (fast rcp)
 * ================================================================= */
__global__ void __launch_bounds__(256) rsumk(
    const float* __restrict__ dist, float* __restrict__ out)
{
    const int row = blockIdx.x;
    const float4* p = (const float4*)(dist + (size_t)row * 2048);
    const int t = threadIdx.x;

    float s = 0.f;
#pragma unroll
    for (int it = 0; it < 2; it++) {
        float4 x = p[t + it * 256];
        s += __fdividef(1.0f, x.x + EPSV) + __fdividef(1.0f, x.y + EPSV)
           + __fdividef(1.0f, x.z + EPSV) + __fdividef(1.0f, x.w + EPSV);
    }
#pragma unroll
    for (int off = 16; off > 0; off >>= 1)
        s += __shfl_xor_sync(0xffffffffu, s, off);

    __shared__ float red[8];
    if ((t & 31) == 0) red[t >> 5] = s;
    __syncthreads();
    if (t == 0) {
        float tot = 0.f;
#pragma unroll
        for (int w = 0; w < 8; w++) tot += red[w];
        out[row] = 1.0f / tot;
    }
}

/* =================================================================
 * Fused attention. Block = (batch b, 32 q-rows, 8 heads). warp = head.
 * Thread tile 4q x 8s (scores) / 4q x 8d (output).
 * P matrix is staged through the (dead-after-QK) per-head sKt slice:
 *   no p[] register array, no PV shuffles, no spills.
 * ================================================================= */
#define ATTN_SMEM_FLOATS (8192 + 9216 + 8192 + 1280 + 32)

__global__ void __launch_bounds__(256, 2) attnk(
    const float* __restrict__ Q, const float* __restrict__ K,
    const float* __restrict__ V, const float* __restrict__ DIST,
    const float* __restrict__ RS, float* __restrict__ O)
{
    extern __shared__ float sm[];
    float* sQt = sm;            /* [256 dims][32 q]                       */
    float* sKt = sm + 8192;     /* [256 dims][32 s] stride 36 (+P reuse)  */
    float* sV  = sm + 17408;    /* [32 s][256 dims]                       */
    float* sW  = sm + 25600;    /* [32 q][32 s] stride 40                 */
    float* sRs = sm + 26880;    /* [32 q]                                 */

    const int b  = blockIdx.y;
    const int qb = blockIdx.x * 32;
    const int t  = threadIdx.x;
    const int lane = t & 31, h = t >> 5;
    const int uq = lane & 7, us = lane >> 3;
    const int q0 = uq * 4, s0 = us * 8, d0 = us * 8;
    const int kb = h * 32;
    float* sP = sKt + kb * 36;  /* per-head P: [32 q][stride 33], fits 32*36 slice */

    /* ---- fill Q transposed (scale folded) + rs ---- */
    {
        const int qq = t & 31, dc = (t >> 5) * 32;
        const float* src = Q + (size_t)(b * SEQ + qb + qq) * 256 + dc;
#pragma unroll
        for (int c = 0; c < 8; c++) {
            float4 x = *(const float4*)(src + c * 4);
            int d = dc + c * 4;
            sQt[(d + 0) * 32 + qq] = x.x * SCALE;
            sQt[(d + 1) * 32 + qq] = x.y * SCALE;
            sQt[(d + 2) * 32 + qq] = x.z * SCALE;
            sQt[(d + 3) * 32 + qq] = x.w * SCALE;
        }
        if (t < 32) sRs[t] = RS[b * SEQ + qb + t];
    }
    __syncthreads();

    ull oacc[4][4];
#pragma unroll
    for (int i = 0; i < 4; i++)
#pragma unroll
        for (int j = 0; j < 4; j++) oacc[i][j] = 0ull;
    float rden[4] = {0.f, 0.f, 0.f, 0.f};

    for (int st = 0; st < 64; st++) {
        const int sb = st * 32;

        /* ---- fill K transposed ---- */
        {
            const int ss = t & 31, dc = (t >> 5) * 32;
            const float* src = K + (size_t)(sb + ss) * 256 + dc;
#pragma unroll
            for (int c = 0; c < 8; c++) {
                float4 x = *(const float4*)(src + c * 4);
                int d = dc + c * 4;
                sKt[(d + 0) * 36 + ss] = x.x;
                sKt[(d + 1) * 36 + ss] = x.y;
                sKt[(d + 2) * 36 + ss] = x.z;
                sKt[(d + 3) * 36 + ss] = x.w;
            }
        }
        /* ---- fill V row-major ---- */
        {
            const int ss = t >> 3, dc = (t & 7) * 32;
            const float4* src = (const float4*)(V + (size_t)(b * SEQ + sb + ss) * 256 + dc);
            float4* dst = (float4*)(sV + ss * 256 + dc);
#pragma unroll
            for (int c = 0; c < 8; c++) dst[c] = src[c];
        }
        /* ---- fill distance weights w = rs / (d + eps)  (fast rcp) ---- */
        {
            const int qq = t >> 3, sc = (t & 7) * 4;
            float4 dd = *(const float4*)(DIST + (size_t)(b * SEQ + qb + qq) * 2048 + sb + sc);
            float rs = sRs[qq];
            float4 w;
            w.x = __fdividef(rs, dd.x + EPSV);
            w.y = __fdividef(rs, dd.y + EPSV);
            w.z = __fdividef(rs, dd.z + EPSV);
            w.w = __fdividef(rs, dd.w + EPSV);
            *(float4*)&sW[qq * 40 + sc] = w;
        }
        __syncthreads();

        /* ---- QK^T scores: 32x32 per head, f32x2 over s-pairs ---- */
        ull racc[4][4];
#pragma unroll
        for (int i = 0; i < 4; i++)
#pragma unroll
            for (int j = 0; j < 4; j++) racc[i][j] = 0ull;

#pragma unroll 4
        for (int c = 0; c < 32; c++) {
            float4 qv = *(const float4*)&sQt[(kb + c) * 32 + q0];
            ulonglong2 b0 = *(const ulonglong2*)&sKt[(kb + c) * 36 + s0];
            ulonglong2 b1 = *(const ulonglong2*)&sKt[(kb + c) * 36 + s0 + 4];
            ull a;
            a = pk2(qv.x, qv.x);
            racc[0][0] = fma2(a, b0.x, racc[0][0]); racc[0][1] = fma2(a, b0.y, racc[0][1]);
            racc[0][2] = fma2(a, b1.x, racc[0][2]); racc[0][3] = fma2(a, b1.y, racc[0][3]);
            a = pk2(qv.y, qv.y);
            racc[1][0] = fma2(a, b0.x, racc[1][0]); racc[1][1] = fma2(a, b0.y, racc[1][1]);
            racc[1][2] = fma2(a, b1.x, racc[1][2]); racc[1][3] = fma2(a, b1.y, racc[1][3]);
            a = pk2(qv.z, qv.z);
            racc[2][0] = fma2(a, b0.x, racc[2][0]); racc[2][1] = fma2(a, b0.y, racc[2][1]);
            racc[2][2] = fma2(a, b1.x, racc[2][2]); racc[2][3] = fma2(a, b1.y, racc[2][3]);
            a = pk2(qv.w, qv.w);
            racc[3][0] = fma2(a, b0.x, racc[3][0]); racc[3][1] = fma2(a, b0.y, racc[3][1]);
            racc[3][2] = fma2(a, b1.x, racc[3][2]); racc[3][3] = fma2(a, b1.y, racc[3][3]);
        }

        /* warp-level fence: all lanes done reading this head's sKt slice
           before we overwrite it with P */
        __syncwarp();

        /* ---- p = exp(score * dw); stage P into the dead sKt slice ---- */
#pragma unroll
        for (int i = 0; i < 4; i++) {
            const float* wr = &sW[(q0 + i) * 40 + s0];
            float4 wa = *(const float4*)wr;
            float4 wb = *(const float4*)(wr + 4);
            float2 x0 = upk(racc[i][0]), x1 = upk(racc[i][1]);
            float2 x2 = upk(racc[i][2]), x3 = upk(racc[i][3]);
            float p0 = __expf(x0.x * wa.x), p1 = __expf(x0.y * wa.y);
            float p2 = __expf(x1.x * wa.z), p3 = __expf(x1.y * wa.w);
            float p4 = __expf(x2.x * wb.x), p5 = __expf(x2.y * wb.y);
            float p6 = __expf(x3.x * wb.z), p7 = __expf(x3.y * wb.w);
            float dl = ((p0 + p1) + (p2 + p3)) + ((p4 + p5) + (p6 + p7));
            dl += __shfl_xor_sync(0xffffffffu, dl, 8);
            dl += __shfl_xor_sync(0xffffffffu, dl, 16);
            rden[i] += dl;
            float* pp = &sP[(q0 + i) * 33 + s0];
            pp[0] = p0; pp[1] = p1; pp[2] = p2; pp[3] = p3;
            pp[4] = p4; pp[5] = p5; pp[6] = p6; pp[7] = p7;
        }
        __syncwarp();

        /* ---- P @ V : p via conflict-free scalar LDS broadcast ---- */
#pragma unroll 4
        for (int s = 0; s < 32; s++) {
            const float* vr = &sV[s * 256 + kb + d0];
            ulonglong2 v0 = *(const ulonglong2*)vr;
            ulonglong2 v1 = *(const ulonglong2*)(vr + 4);
#pragma unroll
            for (int i = 0; i < 4; i++) {
                float pi = sP[(q0 + i) * 33 + s];
                ull a = pk2(pi, pi);
                oacc[i][0] = fma2(a, v0.x, oacc[i][0]);
                oacc[i][1] = fma2(a, v0.y, oacc[i][1]);
                oacc[i][2] = fma2(a, v1.x, oacc[i][2]);
                oacc[i][3] = fma2(a, v1.y, oacc[i][3]);
            }
        }
        __syncthreads();
    }

    /* ---- normalize + write ---- */
#pragma unroll
    for (int i = 0; i < 4; i++) {
        float inv = 1.0f / rden[i];
        float2 o0 = upk(oacc[i][0]), o1 = upk(oacc[i][1]);
        float2 o2 = upk(oacc[i][2]), o3 = upk(oacc[i][3]);
        float4 w0, w1;
        w0.x = o0.x * inv; w0.y = o0.y * inv; w0.z = o1.x * inv; w0.w = o1.y * inv;
        w1.x = o2.x * inv; w1.y = o2.y * inv; w1.z = o3.x * inv; w1.w = o3.y * inv;
        float* dst = O + (size_t)(b * SEQ + qb + q0 + i) * 256 + kb + d0;
        *(float4*)dst       = w0;
        *(float4*)(dst + 4) = w1;
    }
}

/* ================================================================= */
extern "C" void kernel_launch(void* const* d_in, const int* in_sizes, int n_in,
                              void* d_out, int out_size)
{
    const float* query  = (const float*)d_in[0];
    const float* values = (const float*)d_in[1];
    const float* dist   = (const float*)d_in[2];
    const float* Wq     = (const float*)d_in[3];
    const float* Wqb    = (const float*)d_in[4];
    const float* Wk     = (const float*)d_in[5];
    const float* Wkb    = (const float*)d_in[6];
    const float* Wv     = (const float*)d_in[7];
    const float* Wvb    = (const float*)d_in[8];
    const float* fcw    = (const float*)d_in[9];
    const float* fcb    = (const float*)d_in[10];
    const float* keys   = (const float*)d_in[11];
    float* out = (float*)d_out;

    void *pq, *pk, *pv, *prs, *po;
    cudaGetSymbolAddress(&pq,  g_q);
    cudaGetSymbolAddress(&pk,  g_k);
    cudaGetSymbolAddress(&pv,  g_v);
    cudaGetSymbolAddress(&prs, g_rs);
    cudaGetSymbolAddress(&po,  g_o);

    const int smem_bytes = ATTN_SMEM_FLOATS * 4;  /* 107648 */
    cudaFuncSetAttribute(attnk, cudaFuncAttributeMaxDynamicSharedMemorySize, smem_bytes);

    /* all three projections in one launch */
    gemm_proj<<<dim3(128, 4, 3), 256>>>(query,  Wq, Wqb, (float*)pq,
                                        values, Wv, Wvb, (float*)pv,
                                        keys,   Wk, Wkb, (float*)pk);
    /* distance-weight denominators */
    rsumk<<<NB * SEQ, 256>>>(dist, (float*)prs);
    /* fused attention */
    attnk<<<dim3(64, 4), 256, smem_bytes>>>((const float*)pq, (const float*)pk,
                                            (const float*)pv, dist,
                                            (const float*)prs, (float*)po);
    /* output projection */
    gemm256<<<dim3(128, 4), 256>>>((const float*)po, fcw, fcb, out);
}

// round 5
// speedup vs baseline: 3.0670x; 3.0593x over previous
#include <cuda_runtime.h>
#include <cstdint>

#define D_MODEL 256
#define NHEAD 8
#define SEQ 2048
#define NB 4
#define EPSV 1e-9f
#define SCALE 0.17677669529663687f
typedef unsigned long long ull;

__device__ float g_q [NB*SEQ*D_MODEL];
__device__ float g_k [SEQ*D_MODEL];
__device__ float g_v [NB*SEQ*D_MODEL];
__device__ float g_rs[NB*SEQ];
__device__ float g_o [NB*SEQ*D_MODEL];

/* ---- f32x2 helpers (SIMT GEMMs) ---- */
__device__ __forceinline__ ull pk2(float x, float y){ull r;asm("mov.b64 %0,{%1,%2};":"=l"(r):"f"(x),"f"(y));return r;}
__device__ __forceinline__ ull fma2(ull a,ull b,ull c){ull d;asm("fma.rn.f32x2 %0,%1,%2,%3;":"=l"(d):"l"(a),"l"(b),"l"(c));return d;}
__device__ __forceinline__ float2 upk(ull v){float x,y;asm("mov.b64 {%0,%1},%2;":"=f"(x),"=f"(y):"l"(v));float2 r;r.x=x;r.y=y;return r;}

/* ---- tf32 helpers ---- */
__device__ __forceinline__ float rna(float x){uint32_t r;asm("cvt.rna.tf32.f32 %0, %1;":"=r"(r):"f"(x));return __uint_as_float(r);}
__device__ __forceinline__ void mma8(float* c, const float* a, unsigned b0, unsigned b1){
    asm volatile("mma.sync.aligned.m16n8k8.row.col.f32.tf32.tf32.f32 "
        "{%0,%1,%2,%3},{%4,%5,%6,%7},{%8,%9},{%0,%1,%2,%3};"
        : "+f"(c[0]),"+f"(c[1]),"+f"(c[2]),"+f"(c[3])
        : "r"(__float_as_uint(a[0])),"r"(__float_as_uint(a[1])),
          "r"(__float_as_uint(a[2])),"r"(__float_as_uint(a[3])),
          "r"(b0),"r"(b1));
}

/* ======================= SIMT GEMMs (projections + fc) ======================= */
__device__ __forceinline__ void gemm_body(const float* __restrict__ A,const float* __restrict__ W,
    const float* __restrict__ bias,float* __restrict__ C,int row0,int col0,float* sA,float* sB)
{
    const int t=threadIdx.x, tx=t&15, ty=t>>4, m0=ty*4, n0=tx*4;
    ull acc[4][2];
#pragma unroll
    for(int i=0;i<4;i++){acc[i][0]=0;acc[i][1]=0;}
    const int fm=t>>2, fk=(t&3)*8, fn=t&63, fkc=(t>>6)*8;
    for(int kt=0;kt<8;kt++){
        const float4* pa=(const float4*)(A+(size_t)(row0+fm)*256+kt*32+fk);
        float4 a0=pa[0],a1=pa[1];
        *(float4*)&sA[fm*36+fk]=a0; *(float4*)&sA[fm*36+fk+4]=a1;
        const float4* pw=(const float4*)(W+(size_t)(col0+fn)*256+kt*32+fkc);
        float4 w0=pw[0],w1=pw[1];
        sB[(fkc+0)*64+fn]=w0.x;sB[(fkc+1)*64+fn]=w0.y;sB[(fkc+2)*64+fn]=w0.z;sB[(fkc+3)*64+fn]=w0.w;
        sB[(fkc+4)*64+fn]=w1.x;sB[(fkc+5)*64+fn]=w1.y;sB[(fkc+6)*64+fn]=w1.z;sB[(fkc+7)*64+fn]=w1.w;
        __syncthreads();
#pragma unroll
        for(int k4=0;k4<8;k4++){
            float4 av[4];
#pragma unroll
            for(int i=0;i<4;i++) av[i]=*(const float4*)&sA[(m0+i)*36+k4*4];
#pragma unroll
            for(int c=0;c<4;c++){
                ulonglong2 bb=*(const ulonglong2*)&sB[(k4*4+c)*64+n0];
#pragma unroll
                for(int i=0;i<4;i++){
                    float a=(c==0)?av[i].x:(c==1)?av[i].y:(c==2)?av[i].z:av[i].w;
                    ull ad=pk2(a,a);
                    acc[i][0]=fma2(ad,bb.x,acc[i][0]); acc[i][1]=fma2(ad,bb.y,acc[i][1]);
                }
            }
        }
        __syncthreads();
    }
    float4 bi=*(const float4*)&bias[col0+n0];
#pragma unroll
    for(int i=0;i<4;i++){
        float2 r0=upk(acc[i][0]),r1=upk(acc[i][1]);
        float4 o;o.x=r0.x+bi.x;o.y=r0.y+bi.y;o.z=r1.x+bi.z;o.w=r1.y+bi.w;
        *(float4*)&C[(size_t)(row0+m0+i)*256+col0+n0]=o;
    }
}
__global__ void __launch_bounds__(256) gemm256(const float* __restrict__ A,const float* __restrict__ W,
    const float* __restrict__ bias,float* __restrict__ C){
    __shared__ float sA[64*36]; __shared__ float sB[32*64];
    gemm_body(A,W,bias,C,blockIdx.x*64,blockIdx.y*64,sA,sB);
}
__global__ void __launch_bounds__(256) gemm_proj(
    const float* __restrict__ Aq,const float* __restrict__ Wq,const float* __restrict__ bq,float* __restrict__ Cq,
    const float* __restrict__ Av,const float* __restrict__ Wv,const float* __restrict__ bv,float* __restrict__ Cv,
    const float* __restrict__ Ak,const float* __restrict__ Wk,const float* __restrict__ bk,float* __restrict__ Ck){
    __shared__ float sA[64*36]; __shared__ float sB[32*64];
    const int z=blockIdx.z;
    if(z==0) gemm_body(Aq,Wq,bq,Cq,blockIdx.x*64,blockIdx.y*64,sA,sB);
    else if(z==1) gemm_body(Av,Wv,bv,Cv,blockIdx.x*64,blockIdx.y*64,sA,sB);
    else { if(blockIdx.x>=32) return; gemm_body(Ak,Wk,bk,Ck,blockIdx.x*64,blockIdx.y*64,sA,sB); }
}
__global__ void __launch_bounds__(256) rsumk(const float* __restrict__ dist,float* __restrict__ out){
    const int row=blockIdx.x, t=threadIdx.x;
    const float4* p=(const float4*)(dist+(size_t)row*2048);
    float s=0.f;
#pragma unroll
    for(int it=0;it<2;it++){
        float4 x=p[t+it*256];
        s+=__fdividef(1.f,x.x+EPSV)+__fdividef(1.f,x.y+EPSV)+__fdividef(1.f,x.z+EPSV)+__fdividef(1.f,x.w+EPSV);
    }
#pragma unroll
    for(int off=16;off>0;off>>=1) s+=__shfl_xor_sync(0xffffffffu,s,off);
    __shared__ float red[8];
    if((t&31)==0) red[t>>5]=s;
    __syncthreads();
    if(t==0){float tot=0.f;
#pragma unroll
        for(int w=0;w<8;w++) tot+=red[w];
        out[row]=1.f/tot;}
}

/* ======================= tf32 mma.sync fused attention =======================
 * CTA: 64 q-rows x 8 heads, 512 threads. warp = (head h, q-half).
 * Q fragments persist in registers across all 64 s-tiles.
 * smem floats: K 10240 | V 10240 | P 16x1280 | W 2560 | rs 64
 */
#define SKO 0
#define SVO 10240
#define SPO 20480
#define SWO 40960
#define SRS 43520
#define ATTN_SMEM_BYTES (43584*4)

__global__ void __launch_bounds__(512) attnk(
    const float* __restrict__ Qg, const float* __restrict__ Kg,
    const float* __restrict__ Vg, const float* __restrict__ DIST,
    const float* __restrict__ RS, float* __restrict__ O)
{
    extern __shared__ float sm[];
    const int t=threadIdx.x, wid=t>>5, lane=t&31;
    const int h=wid&7, half=wid>>3, g=lane>>2, tg=lane&3;
    const int qb=blockIdx.x*64, b=blockIdx.y;
    const int qw=qb+half*32;
    float* sPw=&sm[SPO+wid*1280];

    if(t<64) sm[SRS+t]=RS[b*SEQ+qb+t];

    /* Q fragments: [mt][kt][4], rna(x*SCALE) folded */
    float aq[2][4][4];
    {
        const float* Qb=Qg+((size_t)(b*SEQ+qw))*256+h*32;
#pragma unroll
        for(int mt=0;mt<2;mt++)
#pragma unroll
        for(int kt=0;kt<4;kt++){
            int r0=mt*16+g, r1=r0+8, c0=kt*8+tg, c1=c0+4;
            aq[mt][kt][0]=rna(Qb[(size_t)r0*256+c0]*SCALE);
            aq[mt][kt][1]=rna(Qb[(size_t)r1*256+c0]*SCALE);
            aq[mt][kt][2]=rna(Qb[(size_t)r0*256+c1]*SCALE);
            aq[mt][kt][3]=rna(Qb[(size_t)r1*256+c1]*SCALE);
        }
    }

    float oc[2][4][4];
#pragma unroll
    for(int mt=0;mt<2;mt++)
#pragma unroll
    for(int nt=0;nt<4;nt++)
#pragma unroll
    for(int i=0;i<4;i++) oc[mt][nt][i]=0.f;
    float rden[2][2]={{0.f,0.f},{0.f,0.f}};
    __syncthreads();

    for(int st=0; st<64; st++){
        const int sb=st*32;
        /* K,V tiles: per-head [32 s][40] rows, rna'd */
#pragma unroll
        for(int it=0;it<4;it++){
            int i=t+it*512, s=i>>6, e4=(i&63)<<2, hh=e4>>5, c=e4&31;
            float4 x=*(const float4*)&Kg[(size_t)(sb+s)*256+e4];
            float4 y; y.x=rna(x.x);y.y=rna(x.y);y.z=rna(x.z);y.w=rna(x.w);
            *(float4*)&sm[SKO+hh*1280+s*40+c]=y;
            float4 v=*(const float4*)&Vg[((size_t)(b*SEQ+sb+s))*256+e4];
            float4 w; w.x=rna(v.x);w.y=rna(v.y);w.z=rna(v.z);w.w=rna(v.w);
            *(float4*)&sm[SVO+hh*1280+s*40+c]=w;
        }
        /* dw tile: [64 q][40] */
        {
            int q=t>>3, s4=(t&7)<<2;
            float4 dd=*(const float4*)&DIST[((size_t)(b*SEQ+qb+q))*2048+sb+s4];
            float rs=sm[SRS+q];
            float4 w;
            w.x=__fdividef(rs,dd.x+EPSV); w.y=__fdividef(rs,dd.y+EPSV);
            w.z=__fdividef(rs,dd.z+EPSV); w.w=__fdividef(rs,dd.w+EPSV);
            *(float4*)&sm[SWO+q*40+s4]=w;
        }
        __syncthreads();

        /* QK^T: S[32q x 32s] per warp */
        float sc[2][4][4];
#pragma unroll
        for(int mt=0;mt<2;mt++)
#pragma unroll
        for(int nt=0;nt<4;nt++)
#pragma unroll
        for(int i=0;i<4;i++) sc[mt][nt][i]=0.f;
#pragma unroll
        for(int kt=0;kt<4;kt++)
#pragma unroll
        for(int nt=0;nt<4;nt++){
            const float* kp=&sm[SKO+h*1280+(nt*8+g)*40+kt*8+tg];
            unsigned b0=__float_as_uint(kp[0]), b1=__float_as_uint(kp[4]);
            mma8(sc[0][nt],aq[0][kt],b0,b1);
            mma8(sc[1][nt],aq[1][kt],b0,b1);
        }

        /* p = rna(exp(score*dw)); den; stage P in warp-private smem */
#pragma unroll
        for(int mt=0;mt<2;mt++){
            float d0=0.f,d1=0.f;
            int qr=half*32+mt*16+g;
#pragma unroll
            for(int nt=0;nt<4;nt++){
                float2 w0=*(const float2*)&sm[SWO+qr*40+nt*8+2*tg];
                float2 w1=*(const float2*)&sm[SWO+(qr+8)*40+nt*8+2*tg];
                float p0=rna(__expf(sc[mt][nt][0]*w0.x));
                float p1=rna(__expf(sc[mt][nt][1]*w0.y));
                float p2=rna(__expf(sc[mt][nt][2]*w1.x));
                float p3=rna(__expf(sc[mt][nt][3]*w1.y));
                d0+=p0+p1; d1+=p2+p3;
                float2 q01; q01.x=p0; q01.y=p1;
                float2 q23; q23.x=p2; q23.y=p3;
                *(float2*)&sPw[(mt*16+g)*40+nt*8+2*tg]=q01;
                *(float2*)&sPw[(mt*16+g+8)*40+nt*8+2*tg]=q23;
            }
            rden[mt][0]+=d0; rden[mt][1]+=d1;
        }
        __syncwarp();

        /* O += P @ V */
#pragma unroll
        for(int kt=0;kt<4;kt++){
            float ap[2][4];
#pragma unroll
            for(int mt=0;mt<2;mt++){
                ap[mt][0]=sPw[(mt*16+g)*40+kt*8+tg];
                ap[mt][1]=sPw[(mt*16+g+8)*40+kt*8+tg];
                ap[mt][2]=sPw[(mt*16+g)*40+kt*8+tg+4];
                ap[mt][3]=sPw[(mt*16+g+8)*40+kt*8+tg+4];
            }
#pragma unroll
            for(int nt=0;nt<4;nt++){
                const float* vp=&sm[SVO+h*1280+(kt*8+tg)*40+nt*8+g];
                unsigned b0=__float_as_uint(vp[0]), b1=__float_as_uint(vp[160]);
                mma8(oc[0][nt],ap[0],b0,b1);
                mma8(oc[1][nt],ap[1],b0,b1);
            }
        }
        __syncthreads();
    }

    /* reduce denominators across quad, normalize, write */
#pragma unroll
    for(int mt=0;mt<2;mt++)
#pragma unroll
    for(int r=0;r<2;r++){
        float v=rden[mt][r];
        v+=__shfl_xor_sync(0xffffffffu,v,1);
        v+=__shfl_xor_sync(0xffffffffu,v,2);
        rden[mt][r]=__fdividef(1.f,v);
    }
#pragma unroll
    for(int mt=0;mt<2;mt++)
#pragma unroll
    for(int nt=0;nt<4;nt++){
        size_t r0=((size_t)(b*SEQ+qw+mt*16+g))*256+h*32+nt*8+2*tg;
        float2 o0; o0.x=oc[mt][nt][0]*rden[mt][0]; o0.y=oc[mt][nt][1]*rden[mt][0];
        float2 o1; o1.x=oc[mt][nt][2]*rden[mt][1]; o1.y=oc[mt][nt][3]*rden[mt][1];
        *(float2*)&O[r0]=o0;
        *(float2*)&O[r0+8*256]=o1;
    }
}

/* ================================================================= */
extern "C" void kernel_launch(void* const* d_in, const int* in_sizes, int n_in,
                              void* d_out, int out_size)
{
    const float* query=(const float*)d_in[0];
    const float* values=(const float*)d_in[1];
    const float* dist=(const float*)d_in[2];
    const float* Wq=(const float*)d_in[3];  const float* Wqb=(const float*)d_in[4];
    const float* Wk=(const float*)d_in[5];  const float* Wkb=(const float*)d_in[6];
    const float* Wv=(const float*)d_in[7];  const float* Wvb=(const float*)d_in[8];
    const float* fcw=(const float*)d_in[9]; const float* fcb=(const float*)d_in[10];
    const float* keys=(const float*)d_in[11];
    float* out=(float*)d_out;

    void *pq,*pk,*pv,*prs,*po;
    cudaGetSymbolAddress(&pq,g_q);   cudaGetSymbolAddress(&pk,g_k);
    cudaGetSymbolAddress(&pv,g_v);   cudaGetSymbolAddress(&prs,g_rs);
    cudaGetSymbolAddress(&po,g_o);

    cudaFuncSetAttribute(attnk, cudaFuncAttributeMaxDynamicSharedMemorySize, ATTN_SMEM_BYTES);

    gemm_proj<<<dim3(128,4,3),256>>>(query,Wq,Wqb,(float*)pq,
                                     values,Wv,Wvb,(float*)pv,
                                     keys,Wk,Wkb,(float*)pk);
    rsumk<<<NB*SEQ,256>>>(dist,(float*)prs);
    attnk<<<dim3(32,NB),512,ATTN_SMEM_BYTES>>>((const float*)pq,(const float*)pk,
        (const float*)pv,dist,(const float*)prs,(float*)po);
    gemm256<<<dim3(128,4),256>>>((const float*)po,fcw,fcb,out);
}

// round 6
// speedup vs baseline: 3.5417x; 1.1548x over previous
#include <cuda_runtime.h>
#include <cstdint>

#define D_MODEL 256
#define NHEAD 8
#define SEQ 2048
#define NB 4
#define EPSV 1e-9f
#define SCALE 0.17677669529663687f

__device__ float g_q [NB*SEQ*D_MODEL];
__device__ float g_k [SEQ*D_MODEL];
__device__ float g_v [NB*SEQ*D_MODEL];
__device__ float g_rs[NB*SEQ];
__device__ float g_o [NB*SEQ*D_MODEL];

/* ---- tf32 / mma helpers ---- */
__device__ __forceinline__ float rna(float x){uint32_t r;asm("cvt.rna.tf32.f32 %0, %1;":"=r"(r):"f"(x));return __uint_as_float(r);}
__device__ __forceinline__ void mma8(float* c, const float* a, unsigned b0, unsigned b1){
    asm volatile("mma.sync.aligned.m16n8k8.row.col.f32.tf32.tf32.f32 "
        "{%0,%1,%2,%3},{%4,%5,%6,%7},{%8,%9},{%0,%1,%2,%3};"
        : "+f"(c[0]),"+f"(c[1]),"+f"(c[2]),"+f"(c[3])
        : "r"(__float_as_uint(a[0])),"r"(__float_as_uint(a[1])),
          "r"(__float_as_uint(a[2])),"r"(__float_as_uint(a[3])),
          "r"(b0),"r"(b1));
}
__device__ __forceinline__ uint32_t smem_u32(const void* p){uint32_t a;asm("{ .reg .u64 t; cvta.to.shared.u64 t, %1; cvt.u32.u64 %0, t; }":"=r"(a):"l"(p));return a;}
__device__ __forceinline__ void cpa16(uint32_t dst, const void* src){
    asm volatile("cp.async.cg.shared.global [%0], [%1], 16;"::"r"(dst),"l"(src):"memory");}
#define CPCOMMIT() asm volatile("cp.async.commit_group;":::"memory")
#define CPWAIT1()  asm volatile("cp.async.wait_group 1;":::"memory")
#define CPWAIT0()  asm volatile("cp.async.wait_group 0;":::"memory")

/* ======================= 3xTF32 tensor GEMM: C = A @ W^T + bias =======================
 * CTA 128m x 64n, 256 thr, 8 warps (wm 0..3, wn 0..1), warp tile 32x32.
 * roundout: round C to tf32 (for q/k/v feeding attnk).
 */
#define GT_SMEM_BYTES (13824*4)
__device__ __forceinline__ void gemm3t_body(const float* __restrict__ A,const float* __restrict__ W,
    const float* __restrict__ bias,float* __restrict__ C,int row0,int col0,int roundout,float* s)
{
    float* sAb=s; float* sAs=s+4608; float* sWb=s+9216; float* sWs=s+11520;
    const int t=threadIdx.x, lane=t&31, w=t>>5, g=lane>>2, tg=lane&3;
    const int m0=(w&3)*32, n0=(w>>2)*32;
    float oc[2][4][4];
#pragma unroll
    for(int mt=0;mt<2;mt++)
#pragma unroll
    for(int nt=0;nt<4;nt++)
#pragma unroll
    for(int i=0;i<4;i++) oc[mt][nt][i]=0.f;

    for(int kc=0;kc<8;kc++){
#pragma unroll
        for(int it=0;it<4;it++){
            int i=t+it*256, m=i>>3, k4=(i&7)<<2;
            float4 x=*(const float4*)&A[(size_t)(row0+m)*256+kc*32+k4];
            float4 bg,sml;
            bg.x=rna(x.x);bg.y=rna(x.y);bg.z=rna(x.z);bg.w=rna(x.w);
            sml.x=rna(x.x-bg.x);sml.y=rna(x.y-bg.y);sml.z=rna(x.z-bg.z);sml.w=rna(x.w-bg.w);
            *(float4*)&sAb[m*36+k4]=bg; *(float4*)&sAs[m*36+k4]=sml;
        }
#pragma unroll
        for(int it=0;it<2;it++){
            int i=t+it*256, n=i>>3, k4=(i&7)<<2;
            float4 x=*(const float4*)&W[(size_t)(col0+n)*256+kc*32+k4];
            float4 bg,sml;
            bg.x=rna(x.x);bg.y=rna(x.y);bg.z=rna(x.z);bg.w=rna(x.w);
            sml.x=rna(x.x-bg.x);sml.y=rna(x.y-bg.y);sml.z=rna(x.z-bg.z);sml.w=rna(x.w-bg.w);
            *(float4*)&sWb[n*36+k4]=bg; *(float4*)&sWs[n*36+k4]=sml;
        }
        __syncthreads();
#pragma unroll
        for(int kt=0;kt<4;kt++){
            float ab[2][4], as_[2][4];
#pragma unroll
            for(int mt=0;mt<2;mt++){
                const float* ap=&sAb[(m0+mt*16+g)*36+kt*8+tg];
                ab[mt][0]=ap[0]; ab[mt][1]=ap[288]; ab[mt][2]=ap[4]; ab[mt][3]=ap[292];
                const float* sp=&sAs[(m0+mt*16+g)*36+kt*8+tg];
                as_[mt][0]=sp[0]; as_[mt][1]=sp[288]; as_[mt][2]=sp[4]; as_[mt][3]=sp[292];
            }
#pragma unroll
            for(int nt=0;nt<4;nt++){
                const float* wp=&sWb[(n0+nt*8+g)*36+kt*8+tg];
                unsigned wb0=__float_as_uint(wp[0]), wb1=__float_as_uint(wp[4]);
                const float* vp=&sWs[(n0+nt*8+g)*36+kt*8+tg];
                unsigned ws0=__float_as_uint(vp[0]), ws1=__float_as_uint(vp[4]);
#pragma unroll
                for(int mt=0;mt<2;mt++){
                    mma8(oc[mt][nt],ab[mt],wb0,wb1);
                    mma8(oc[mt][nt],as_[mt],wb0,wb1);
                    mma8(oc[mt][nt],ab[mt],ws0,ws1);
                }
            }
        }
        __syncthreads();
    }
#pragma unroll
    for(int mt=0;mt<2;mt++)
#pragma unroll
    for(int nt=0;nt<4;nt++){
        int col=col0+n0+nt*8+2*tg;
        float2 bi=*(const float2*)&bias[col];
        float2 o0,o1;
        o0.x=oc[mt][nt][0]+bi.x; o0.y=oc[mt][nt][1]+bi.y;
        o1.x=oc[mt][nt][2]+bi.x; o1.y=oc[mt][nt][3]+bi.y;
        if(roundout){ o0.x=rna(o0.x); o0.y=rna(o0.y); o1.x=rna(o1.x); o1.y=rna(o1.y); }
        size_t r=(size_t)(row0+m0+mt*16+g)*256+col;
        *(float2*)&C[r]=o0;
        *(float2*)&C[r+8*256]=o1;
    }
}
__global__ void __launch_bounds__(256) gemm3t(const float* __restrict__ A,const float* __restrict__ W,
    const float* __restrict__ bias,float* __restrict__ C,int roundout){
    extern __shared__ float s[];
    gemm3t_body(A,W,bias,C,blockIdx.x*128,blockIdx.y*64,roundout,s);
}
__global__ void __launch_bounds__(256) gemm3t_proj(
    const float* __restrict__ Aq,const float* __restrict__ Wq,const float* __restrict__ bq,float* __restrict__ Cq,
    const float* __restrict__ Av,const float* __restrict__ Wv,const float* __restrict__ bv,float* __restrict__ Cv,
    const float* __restrict__ Ak,const float* __restrict__ Wk,const float* __restrict__ bk,float* __restrict__ Ck){
    extern __shared__ float s[];
    const int z=blockIdx.z;
    if(z==0) gemm3t_body(Aq,Wq,bq,Cq,blockIdx.x*128,blockIdx.y*64,1,s);
    else if(z==1) gemm3t_body(Av,Wv,bv,Cv,blockIdx.x*128,blockIdx.y*64,1,s);
    else { if(blockIdx.x>=16) return; gemm3t_body(Ak,Wk,bk,Ck,blockIdx.x*128,blockIdx.y*64,1,s); }
}

/* ---- rs = SCALE / sum(1/(d+eps)) ---- */
__global__ void __launch_bounds__(256) rsumk(const float* __restrict__ dist,float* __restrict__ out){
    const int row=blockIdx.x, t=threadIdx.x;
    const float4* p=(const float4*)(dist+(size_t)row*2048);
    float s=0.f;
#pragma unroll
    for(int it=0;it<2;it++){
        float4 x=p[t+it*256];
        s+=__fdividef(1.f,x.x+EPSV)+__fdividef(1.f,x.y+EPSV)+__fdividef(1.f,x.z+EPSV)+__fdividef(1.f,x.w+EPSV);
    }
#pragma unroll
    for(int off=16;off>0;off>>=1) s+=__shfl_xor_sync(0xffffffffu,s,off);
    __shared__ float red[8];
    if((t&31)==0) red[t>>5]=s;
    __syncthreads();
    if(t==0){float tot=0.f;
#pragma unroll
        for(int w=0;w<8;w++) tot+=red[w];
        out[row]=SCALE/tot;}
}

/* ======================= pipelined tf32 attention =======================
 * 512 thr, warp=(head, q-half). Double-buffered cp.async K/V/dist (raw fp32,
 * q/k/v pre-rounded to tf32 by projections; SCALE folded into rs).
 * smem floats: buf0 K8320|V8320|D2304 @0, buf1 @18944, P 16x1152 @37888. tot 56320.
 */
#define BUFSZ 18944
#define SPOFF 37888
#define ATTN_SMEM_BYTES (56320*4)

__device__ __forceinline__ void attn_fill(const float* __restrict__ Kg,const float* __restrict__ Vg,
    const float* __restrict__ DIST,uint32_t base,int sb,int b,int qb,int t)
{
    uint32_t kb_=base, vb_=base+8320*4, db_=base+16640*4;
#pragma unroll
    for(int it=0;it<4;it++){
        int i=t+it*512, s=i>>6, c4=(i&63)<<2;
        cpa16(kb_+(s*260+c4)*4, Kg+(size_t)(sb+s)*256+c4);
        cpa16(vb_+(s*260+c4)*4, Vg+((size_t)(b*SEQ+sb+s))*256+c4);
    }
    int q=t>>3, s4=(t&7)<<2;
    cpa16(db_+(q*36+s4)*4, DIST+((size_t)(b*SEQ+qb+q))*2048+sb+s4);
}

__global__ void __launch_bounds__(512,1) attnk(
    const float* __restrict__ Qg, const float* __restrict__ Kg,
    const float* __restrict__ Vg, const float* __restrict__ DIST,
    const float* __restrict__ RS, float* __restrict__ O)
{
    extern __shared__ float sm[];
    const int t=threadIdx.x, wid=t>>5, lane=t&31;
    const int h=wid&7, half=wid>>3, g=lane>>2, tg=lane&3;
    const int qb=blockIdx.x*64, b=blockIdx.y, qw=qb+half*32;
    const uint32_t smb=smem_u32(sm);
    float* sPw=&sm[SPOFF+wid*1152];

    /* Q fragments (pre-rounded tf32, raw) */
    float aq[2][4][4];
    {
        const float* Qb=Qg+((size_t)(b*SEQ+qw))*256+h*32;
#pragma unroll
        for(int mt=0;mt<2;mt++)
#pragma unroll
        for(int kt=0;kt<4;kt++){
            int r0=mt*16+g, c0=kt*8+tg;
            aq[mt][kt][0]=Qb[(size_t)r0*256+c0];
            aq[mt][kt][1]=Qb[(size_t)(r0+8)*256+c0];
            aq[mt][kt][2]=Qb[(size_t)r0*256+c0+4];
            aq[mt][kt][3]=Qb[(size_t)(r0+8)*256+c0+4];
        }
    }
    float rsv[4];
#pragma unroll
    for(int mt=0;mt<2;mt++)
#pragma unroll
    for(int r=0;r<2;r++) rsv[mt*2+r]=RS[b*SEQ+qw+mt*16+r*8+g];

    float oc[2][4][4];
#pragma unroll
    for(int mt=0;mt<2;mt++)
#pragma unroll
    for(int nt=0;nt<4;nt++)
#pragma unroll
    for(int i=0;i<4;i++) oc[mt][nt][i]=0.f;
    float rden[2][2]={{0.f,0.f},{0.f,0.f}};

    attn_fill(Kg,Vg,DIST,smb,0,b,qb,t);
    CPCOMMIT();

    for(int st=0; st<64; st++){
        if(st<63){ attn_fill(Kg,Vg,DIST,smb+((st+1)&1)*BUFSZ*4,(st+1)*32,b,qb,t); CPCOMMIT(); CPWAIT1(); }
        else CPWAIT0();
        __syncthreads();
        const float* fK=&sm[(st&1)*BUFSZ];
        const float* fV=fK+8320;
        const float* fD=fK+16640;

        /* QK^T */
        float sc[2][4][4];
#pragma unroll
        for(int mt=0;mt<2;mt++)
#pragma unroll
        for(int nt=0;nt<4;nt++)
#pragma unroll
        for(int i=0;i<4;i++) sc[mt][nt][i]=0.f;
#pragma unroll
        for(int kt=0;kt<4;kt++)
#pragma unroll
        for(int nt=0;nt<4;nt++){
            const float* kp=&fK[(nt*8+g)*260+h*32+kt*8+tg];
            unsigned b0=__float_as_uint(kp[0]), b1=__float_as_uint(kp[4]);
            mma8(sc[0][nt],aq[0][kt],b0,b1);
            mma8(sc[1][nt],aq[1][kt],b0,b1);
        }

        /* p = rna(exp(sc * rs/(d+eps))) -> sPw; den */
#pragma unroll
        for(int mt=0;mt<2;mt++){
            float d0a=0.f,d1a=0.f;
            int qr=half*32+mt*16+g;
            float rs0=rsv[mt*2], rs1=rsv[mt*2+1];
#pragma unroll
            for(int nt=0;nt<4;nt++){
                float2 d0=*(const float2*)&fD[qr*36+nt*8+2*tg];
                float2 d1=*(const float2*)&fD[(qr+8)*36+nt*8+2*tg];
                float p0=rna(__expf(sc[mt][nt][0]*__fdividef(rs0,d0.x+EPSV)));
                float p1=rna(__expf(sc[mt][nt][1]*__fdividef(rs0,d0.y+EPSV)));
                float p2=rna(__expf(sc[mt][nt][2]*__fdividef(rs1,d1.x+EPSV)));
                float p3=rna(__expf(sc[mt][nt][3]*__fdividef(rs1,d1.y+EPSV)));
                d0a+=p0+p1; d1a+=p2+p3;
                float2 q01; q01.x=p0; q01.y=p1;
                float2 q23; q23.x=p2; q23.y=p3;
                *(float2*)&sPw[(mt*16+g)*36+nt*8+2*tg]=q01;
                *(float2*)&sPw[(mt*16+g+8)*36+nt*8+2*tg]=q23;
            }
            rden[mt][0]+=d0a; rden[mt][1]+=d1a;
        }
        __syncwarp();

        /* O += P @ V */
#pragma unroll
        for(int kt=0;kt<4;kt++){
            float ap[2][4];
#pragma unroll
            for(int mt=0;mt<2;mt++){
                ap[mt][0]=sPw[(mt*16+g)*36+kt*8+tg];
                ap[mt][1]=sPw[(mt*16+g+8)*36+kt*8+tg];
                ap[mt][2]=sPw[(mt*16+g)*36+kt*8+tg+4];
                ap[mt][3]=sPw[(mt*16+g+8)*36+kt*8+tg+4];
            }
#pragma unroll
            for(int nt=0;nt<4;nt++){
                const float* vp=&fV[(kt*8+tg)*260+h*32+nt*8+g];
                unsigned b0=__float_as_uint(vp[0]), b1=__float_as_uint(vp[1040]);
                mma8(oc[0][nt],ap[0],b0,b1);
                mma8(oc[1][nt],ap[1],b0,b1);
            }
        }
        __syncthreads();
    }

#pragma unroll
    for(int mt=0;mt<2;mt++)
#pragma unroll
    for(int r=0;r<2;r++){
        float v=rden[mt][r];
        v+=__shfl_xor_sync(0xffffffffu,v,1);
        v+=__shfl_xor_sync(0xffffffffu,v,2);
        rden[mt][r]=__fdividef(1.f,v);
    }
#pragma unroll
    for(int mt=0;mt<2;mt++)
#pragma unroll
    for(int nt=0;nt<4;nt++){
        size_t r0=((size_t)(b*SEQ+qw+mt*16+g))*256+h*32+nt*8+2*tg;
        float2 o0; o0.x=oc[mt][nt][0]*rden[mt][0]; o0.y=oc[mt][nt][1]*rden[mt][0];
        float2 o1; o1.x=oc[mt][nt][2]*rden[mt][1]; o1.y=oc[mt][nt][3]*rden[mt][1];
        *(float2*)&O[r0]=o0;
        *(float2*)&O[r0+8*256]=o1;
    }
}

/* ================================================================= */
extern "C" void kernel_launch(void* const* d_in, const int* in_sizes, int n_in,
                              void* d_out, int out_size)
{
    const float* query=(const float*)d_in[0];
    const float* values=(const float*)d_in[1];
    const float* dist=(const float*)d_in[2];
    const float* Wq=(const float*)d_in[3];  const float* Wqb=(const float*)d_in[4];
    const float* Wk=(const float*)d_in[5];  const float* Wkb=(const float*)d_in[6];
    const float* Wv=(const float*)d_in[7];  const float* Wvb=(const float*)d_in[8];
    const float* fcw=(const float*)d_in[9]; const float* fcb=(const float*)d_in[10];
    const float* keys=(const float*)d_in[11];
    float* out=(float*)d_out;

    void *pq,*pk,*pv,*prs,*po;
    cudaGetSymbolAddress(&pq,g_q);   cudaGetSymbolAddress(&pk,g_k);
    cudaGetSymbolAddress(&pv,g_v);   cudaGetSymbolAddress(&prs,g_rs);
    cudaGetSymbolAddress(&po,g_o);

    cudaFuncSetAttribute(attnk, cudaFuncAttributeMaxDynamicSharedMemorySize, ATTN_SMEM_BYTES);
    cudaFuncSetAttribute(gemm3t, cudaFuncAttributeMaxDynamicSharedMemorySize, GT_SMEM_BYTES);
    cudaFuncSetAttribute(gemm3t_proj, cudaFuncAttributeMaxDynamicSharedMemorySize, GT_SMEM_BYTES);

    gemm3t_proj<<<dim3(64,4,3),256,GT_SMEM_BYTES>>>(query,Wq,Wqb,(float*)pq,
                                                    values,Wv,Wvb,(float*)pv,
                                                    keys,Wk,Wkb,(float*)pk);
    rsumk<<<NB*SEQ,256>>>(dist,(float*)prs);
    attnk<<<dim3(32,NB),512,ATTN_SMEM_BYTES>>>((const float*)pq,(const float*)pk,
        (const float*)pv,dist,(const float*)prs,(float*)po);
    gemm3t<<<dim3(64,4),256,GT_SMEM_BYTES>>>((const float*)po,fcw,fcb,out,0);
}